// round 3
// baseline (speedup 1.0000x reference)
#include <cuda_runtime.h>
#include <stdint.h>

#define N_NODESC 50000
#define N_EDGESC 800000
#define N_GRAPHSC 64
#define HIDC 128
#define OUTC 16

// ---------------- scratch (device globals; no allocation allowed) ----------------
__device__ int   g_is64;
__device__ int   g_deg[N_NODESC];
__device__ float g_dis[N_NODESC];
__device__ float g_hs [(size_t)N_NODESC * HIDC];   // (x@W)*dis  (pre-scaled messages)
__device__ float g_agg[(size_t)N_NODESC * HIDC];   // edge-sum accumulator
__device__ float g_h  [(size_t)N_NODESC * HIDC];   // layer output
__device__ float g_pool[N_GRAPHSC * HIDC];
__device__ float g_cnt [N_GRAPHSC];

__device__ __forceinline__ int load_index(const void* p, long long i) {
    if (g_is64) return (int)((const long long*)p)[i];
    return ((const int*)p)[i];
}

__device__ __forceinline__ void red_add_v4(float* addr, float4 v) {
    asm volatile("red.global.add.v4.f32 [%0], {%1,%2,%3,%4};"
                 :: "l"(addr), "f"(v.x), "f"(v.y), "f"(v.z), "f"(v.w) : "memory");
}

// ---------------- dtype width detection (int64 vs silently-downcast int32) -------
__global__ void detect_kernel(const void* eidx) {
    if (threadIdx.x == 0 && blockIdx.x == 0) {
        const long long* q = (const long long*)eidx;
        int is64 = 1;
        for (int i = 0; i < 64; i++) {
            long long v = q[i];
            if (v < 0 || v >= (long long)N_NODESC) { is64 = 0; break; }
        }
        g_is64 = is64;
    }
}

// ---------------- degree / normalization -----------------------------------------
__global__ void deg_init_kernel() {
    int i = blockIdx.x * blockDim.x + threadIdx.x;
    if (i < N_NODESC) g_deg[i] = 1;          // self-loop
}

__global__ void deg_accum_kernel(const void* eidx) {
    int e = blockIdx.x * blockDim.x + threadIdx.x;
    if (e >= N_EDGESC) return;
    int dst = load_index(eidx, (long long)N_EDGESC + e);
    atomicAdd(&g_deg[dst], 1);
}

__global__ void dis_kernel() {
    int i = blockIdx.x * blockDim.x + threadIdx.x;
    if (i < N_NODESC) g_dis[i] = rsqrtf((float)g_deg[i]);
}

// ---------------- GEMM: C[r,:] = (A[r,:] @ W) * dis[r]  (M x 128 x 128) ----------
__global__ __launch_bounds__(256)
void gemm_scale_kernel(const float* __restrict__ A, const float* __restrict__ W,
                       float* __restrict__ C, int M) {
    __shared__ float As[8][128];
    __shared__ float Bs[8][128];
    const int tid  = threadIdx.x;
    const int tx   = tid & 15;       // output col group (8 cols each)
    const int ty   = tid >> 4;       // output row group (8 rows each)
    const int row0 = blockIdx.x * 128;

    const int arow = tid >> 1;       // 0..127
    const int acol = (tid & 1) * 4;  // 0 or 4
    const int brow = tid >> 5;       // 0..7
    const int bcol = (tid & 31) * 4; // 0..124

    float acc[8][8];
#pragma unroll
    for (int i = 0; i < 8; i++)
#pragma unroll
        for (int j = 0; j < 8; j++) acc[i][j] = 0.f;

    for (int k0 = 0; k0 < 128; k0 += 8) {
        float4 av = make_float4(0.f, 0.f, 0.f, 0.f);
        int grow = row0 + arow;
        if (grow < M) av = *(const float4*)(A + (size_t)grow * 128 + k0 + acol);
        As[acol + 0][arow] = av.x;
        As[acol + 1][arow] = av.y;
        As[acol + 2][arow] = av.z;
        As[acol + 3][arow] = av.w;

        float4 bv = *(const float4*)(W + (size_t)(k0 + brow) * 128 + bcol);
        *(float4*)&Bs[brow][bcol] = bv;
        __syncthreads();

#pragma unroll
        for (int k = 0; k < 8; k++) {
            float am[8], bn[8];
            *(float4*)&am[0] = *(const float4*)&As[k][ty * 8 + 0];
            *(float4*)&am[4] = *(const float4*)&As[k][ty * 8 + 4];
            *(float4*)&bn[0] = *(const float4*)&Bs[k][tx * 8 + 0];
            *(float4*)&bn[4] = *(const float4*)&Bs[k][tx * 8 + 4];
#pragma unroll
            for (int i = 0; i < 8; i++)
#pragma unroll
                for (int j = 0; j < 8; j++)
                    acc[i][j] = fmaf(am[i], bn[j], acc[i][j]);
        }
        __syncthreads();
    }

#pragma unroll
    for (int i = 0; i < 8; i++) {
        int r = row0 + ty * 8 + i;
        if (r < M) {
            float s = g_dis[r];
#pragma unroll
            for (int j = 0; j < 8; j += 4) {
                float4 v = make_float4(acc[i][j] * s, acc[i][j + 1] * s,
                                       acc[i][j + 2] * s, acc[i][j + 3] * s);
                *(float4*)(C + (size_t)r * 128 + tx * 8 + j) = v;
            }
        }
    }
}

// ---------------- edge scatter: agg[dst] += hs[src], one warp per edge -----------
__global__ __launch_bounds__(256)
void edge_scatter_kernel(const void* __restrict__ eidx,
                         const float* __restrict__ hs,
                         float* __restrict__ agg) {
    int warp = (blockIdx.x * blockDim.x + threadIdx.x) >> 5;
    int lane = threadIdx.x & 31;
    if (warp >= N_EDGESC) return;
    int src = load_index(eidx, warp);
    int dst = load_index(eidx, (long long)N_EDGESC + warp);
    const float4* hs4 = (const float4*)hs;
    float4 v = hs4[(size_t)src * 32 + lane];
    float* a = agg + (size_t)dst * 128 + lane * 4;
    red_add_v4(a, v);
}

// ---------------- post: h = relu((agg + hs) * dis + b) ---------------------------
__global__ void post_relu_kernel(const float* __restrict__ agg,
                                 const float* __restrict__ hs,
                                 const float* __restrict__ b,
                                 float* __restrict__ hout) {
    int i = blockIdx.x * blockDim.x + threadIdx.x;   // over N*32 float4s
    if (i >= N_NODESC * 32) return;
    int node = i >> 5, c4 = i & 31;
    float s = g_dis[node];
    float4 a  = ((const float4*)agg)[i];
    float4 h  = ((const float4*)hs)[i];
    float4 bb = ((const float4*)b)[c4];
    float4 r;
    r.x = fmaxf(fmaf(a.x + h.x, s, bb.x), 0.f);
    r.y = fmaxf(fmaf(a.y + h.y, s, bb.y), 0.f);
    r.z = fmaxf(fmaf(a.z + h.z, s, bb.z), 0.f);
    r.w = fmaxf(fmaf(a.w + h.w, s, bb.w), 0.f);
    ((float4*)hout)[i] = r;
}

// ---------------- layer-2 post fused with graph pooling --------------------------
__global__ void post_pool_kernel(const void* __restrict__ batch,
                                 const float* __restrict__ agg,
                                 const float* __restrict__ hs,
                                 const float* __restrict__ b,
                                 float* __restrict__ pool) {
    int i = blockIdx.x * blockDim.x + threadIdx.x;
    if (i >= N_NODESC * 32) return;
    int node = i >> 5, c4 = i & 31;
    float s = g_dis[node];
    float4 a  = ((const float4*)agg)[i];
    float4 h  = ((const float4*)hs)[i];
    float4 bb = ((const float4*)b)[c4];
    float4 r;
    r.x = fmaxf(fmaf(a.x + h.x, s, bb.x), 0.f);
    r.y = fmaxf(fmaf(a.y + h.y, s, bb.y), 0.f);
    r.z = fmaxf(fmaf(a.z + h.z, s, bb.z), 0.f);
    r.w = fmaxf(fmaf(a.w + h.w, s, bb.w), 0.f);
    int g = load_index(batch, node);
    red_add_v4(pool + g * HIDC + c4 * 4, r);
}

__global__ void zero_pool_kernel(float* __restrict__ pool, float* __restrict__ cnt) {
    int i = blockIdx.x * blockDim.x + threadIdx.x;
    if (i < N_GRAPHSC * HIDC) pool[i] = 0.f;
    if (i < N_GRAPHSC) cnt[i] = 0.f;
}

__global__ void count_kernel(const void* __restrict__ batch, float* __restrict__ cnt) {
    int i = blockIdx.x * blockDim.x + threadIdx.x;
    if (i >= N_NODESC) return;
    int g = load_index(batch, i);
    atomicAdd(&cnt[g], 1.f);
}

// ---------------- FC head: out = (pool/cnt) @ Wfc + bfc --------------------------
__global__ void final_kernel(const float* __restrict__ pool,
                             const float* __restrict__ cnt,
                             const float* __restrict__ Wfc,
                             const float* __restrict__ bfc,
                             float* __restrict__ out) {
    int t = threadIdx.x;
    if (t >= N_GRAPHSC * OUTC) return;
    int g = t >> 4, o = t & 15;
    float sum = 0.f;
#pragma unroll 8
    for (int c = 0; c < HIDC; c++)
        sum = fmaf(pool[g * HIDC + c], Wfc[c * OUTC + o], sum);
    float c = fmaxf(cnt[g], 1.f);
    out[g * OUTC + o] = sum / c + bfc[o];
}

// ---------------- launcher -------------------------------------------------------
extern "C" void kernel_launch(void* const* d_in, const int* in_sizes, int n_in,
                              void* d_out, int out_size) {
    const float* x    = (const float*)d_in[0];
    const void*  eidx = d_in[1];
    const void*  bat  = d_in[2];
    const float* W1   = (const float*)d_in[3];
    const float* b1   = (const float*)d_in[4];
    const float* W2   = (const float*)d_in[5];
    const float* b2   = (const float*)d_in[6];
    const float* Wfc  = (const float*)d_in[7];
    const float* bfc  = (const float*)d_in[8];
    float* out = (float*)d_out;

    // Resolve REAL device addresses for the scratch globals (host-side symbol
    // references are shadow addresses — the round-2 bug).
    void *p_hs = nullptr, *p_agg = nullptr, *p_h = nullptr, *p_pool = nullptr, *p_cnt = nullptr;
    cudaGetSymbolAddress(&p_hs,   g_hs);
    cudaGetSymbolAddress(&p_agg,  g_agg);
    cudaGetSymbolAddress(&p_h,    g_h);
    cudaGetSymbolAddress(&p_pool, g_pool);
    cudaGetSymbolAddress(&p_cnt,  g_cnt);
    float* hs   = (float*)p_hs;
    float* agg  = (float*)p_agg;
    float* h    = (float*)p_h;
    float* pool = (float*)p_pool;
    float* cnt  = (float*)p_cnt;

    const int T = 256;
    const int nodeBlocks  = (N_NODESC + T - 1) / T;
    const int edgeBlocks  = (N_EDGESC + T - 1) / T;
    const long long edgeThreads = (long long)N_EDGESC * 32;
    const int edgeWarpBlk = (int)((edgeThreads + T - 1) / T);    // warp per edge
    const int chanBlocks  = (N_NODESC * 32 + T - 1) / T;         // float4 per thread
    const int gemmBlocks  = (N_NODESC + 127) / 128;

    detect_kernel<<<1, 64>>>(eidx);
    deg_init_kernel<<<nodeBlocks, T>>>();
    deg_accum_kernel<<<edgeBlocks, T>>>(eidx);
    dis_kernel<<<nodeBlocks, T>>>();

    // ---- layer 1 ----
    cudaMemsetAsync(agg, 0, (size_t)N_NODESC * HIDC * sizeof(float), 0);
    gemm_scale_kernel<<<gemmBlocks, 256>>>(x, W1, hs, N_NODESC);
    edge_scatter_kernel<<<edgeWarpBlk, T>>>(eidx, hs, agg);
    post_relu_kernel<<<chanBlocks, T>>>(agg, hs, b1, h);

    // ---- layer 2 ----
    cudaMemsetAsync(agg, 0, (size_t)N_NODESC * HIDC * sizeof(float), 0);
    gemm_scale_kernel<<<gemmBlocks, 256>>>(h, W2, hs, N_NODESC);
    edge_scatter_kernel<<<edgeWarpBlk, T>>>(eidx, hs, agg);

    // ---- pooling + head ----
    zero_pool_kernel<<<(N_GRAPHSC * HIDC + T - 1) / T, T>>>(pool, cnt);
    count_kernel<<<nodeBlocks, T>>>(bat, cnt);
    post_pool_kernel<<<chanBlocks, T>>>(bat, agg, hs, b2, pool);
    final_kernel<<<1, 1024>>>(pool, cnt, Wfc, bfc, out);
}

// round 4
// speedup vs baseline: 1.0025x; 1.0025x over previous
#include <cuda_runtime.h>
#include <stdint.h>

#define N_NODESC 50000
#define N_EDGESC 800000
#define N_GRAPHSC 64
#define HIDC 128
#define OUTC 16

// ---------------- scratch (device globals; no allocation allowed) ----------------
__device__ int   g_is64;
__device__ int   g_deg[N_NODESC];
__device__ float g_dis[N_NODESC];
__device__ float g_hs [(size_t)N_NODESC * HIDC];   // (x@W)*dis  (pre-scaled messages)
__device__ float g_agg[(size_t)N_NODESC * HIDC];   // accumulator, init = hs (self-loop)
__device__ float g_h  [(size_t)N_NODESC * HIDC];   // layer output
__device__ float g_pool[N_GRAPHSC * HIDC];
__device__ float g_cnt [N_GRAPHSC];

__device__ __forceinline__ int load_index(const void* p, long long i) {
    if (g_is64) return (int)((const long long*)p)[i];
    return ((const int*)p)[i];
}

__device__ __forceinline__ void red_add_v4(float* addr, float4 v) {
    asm volatile("red.global.add.v4.f32 [%0], {%1,%2,%3,%4};"
                 :: "l"(addr), "f"(v.x), "f"(v.y), "f"(v.z), "f"(v.w) : "memory");
}

// ---------------- dtype width detection (int64 vs silently-downcast int32) -------
__global__ void detect_kernel(const void* eidx) {
    if (threadIdx.x == 0 && blockIdx.x == 0) {
        const long long* q = (const long long*)eidx;
        int is64 = 1;
        for (int i = 0; i < 64; i++) {
            long long v = q[i];
            if (v < 0 || v >= (long long)N_NODESC) { is64 = 0; break; }
        }
        g_is64 = is64;
    }
}

// ---------------- degree / normalization -----------------------------------------
__global__ void deg_init_kernel() {
    int i = blockIdx.x * blockDim.x + threadIdx.x;
    if (i < N_NODESC) g_deg[i] = 1;          // self-loop
}

__global__ void deg_accum_kernel(const void* eidx) {
    int e = blockIdx.x * blockDim.x + threadIdx.x;
    if (e >= N_EDGESC) return;
    int dst = load_index(eidx, (long long)N_EDGESC + e);
    atomicAdd(&g_deg[dst], 1);
}

__global__ void dis_kernel() {
    int i = blockIdx.x * blockDim.x + threadIdx.x;
    if (i < N_NODESC) g_dis[i] = rsqrtf((float)g_deg[i]);
}

// ---- GEMM: hs[r,:] = agg[r,:] = (A[r,:] @ W) * dis[r]   (M x 128 x 128) ---------
// K-tile = 16, 128x128 block, 8x8 per thread.
__global__ __launch_bounds__(256)
void gemm_scale_kernel(const float* __restrict__ A, const float* __restrict__ W,
                       float* __restrict__ HS, float* __restrict__ AGG, int M) {
    __shared__ float As[16][128];
    __shared__ float Bs[16][128];
    const int tid  = threadIdx.x;
    const int tx   = tid & 15;       // output col group (8 cols each)
    const int ty   = tid >> 4;       // output row group (8 rows each)
    const int row0 = blockIdx.x * 128;

    float acc[8][8];
#pragma unroll
    for (int i = 0; i < 8; i++)
#pragma unroll
        for (int j = 0; j < 8; j++) acc[i][j] = 0.f;

    for (int k0 = 0; k0 < 128; k0 += 16) {
        // Load A tile: 128 rows x 16 cols = 512 float4 loads, 2 per thread.
#pragma unroll
        for (int u = 0; u < 2; u++) {
            int idx  = tid + u * 256;
            int r    = idx & 127;
            int cg   = idx >> 7;          // 0..3 -> 4-col group
            int grow = row0 + r;
            float4 av = make_float4(0.f, 0.f, 0.f, 0.f);
            if (grow < M) av = *(const float4*)(A + (size_t)grow * 128 + k0 + cg * 4);
            As[cg * 4 + 0][r] = av.x;
            As[cg * 4 + 1][r] = av.y;
            As[cg * 4 + 2][r] = av.z;
            As[cg * 4 + 3][r] = av.w;
        }
        // Load B tile: 16 rows x 128 cols = 512 float4 loads, 2 per thread.
#pragma unroll
        for (int u = 0; u < 2; u++) {
            int idx = tid + u * 256;
            int br  = idx >> 5;           // 0..15
            int bc  = (idx & 31) * 4;     // 0..124
            *(float4*)&Bs[br][bc] = *(const float4*)(W + (size_t)(k0 + br) * 128 + bc);
        }
        __syncthreads();

#pragma unroll
        for (int k = 0; k < 16; k++) {
            float am[8], bn[8];
            *(float4*)&am[0] = *(const float4*)&As[k][ty * 8 + 0];
            *(float4*)&am[4] = *(const float4*)&As[k][ty * 8 + 4];
            *(float4*)&bn[0] = *(const float4*)&Bs[k][tx * 8 + 0];
            *(float4*)&bn[4] = *(const float4*)&Bs[k][tx * 8 + 4];
#pragma unroll
            for (int i = 0; i < 8; i++)
#pragma unroll
                for (int j = 0; j < 8; j++)
                    acc[i][j] = fmaf(am[i], bn[j], acc[i][j]);
        }
        __syncthreads();
    }

#pragma unroll
    for (int i = 0; i < 8; i++) {
        int r = row0 + ty * 8 + i;
        if (r < M) {
            float s = g_dis[r];
#pragma unroll
            for (int j = 0; j < 8; j += 4) {
                float4 v = make_float4(acc[i][j] * s, acc[i][j + 1] * s,
                                       acc[i][j + 2] * s, acc[i][j + 3] * s);
                *(float4*)(HS  + (size_t)r * 128 + tx * 8 + j) = v;
                *(float4*)(AGG + (size_t)r * 128 + tx * 8 + j) = v;  // self-loop init
            }
        }
    }
}

// ---------------- edge scatter: agg[dst] += hs[src], one warp per edge -----------
__global__ __launch_bounds__(256)
void edge_scatter_kernel(const void* __restrict__ eidx,
                         const float* __restrict__ hs,
                         float* __restrict__ agg) {
    int warp = (blockIdx.x * blockDim.x + threadIdx.x) >> 5;
    int lane = threadIdx.x & 31;
    if (warp >= N_EDGESC) return;
    int src = load_index(eidx, warp);
    int dst = load_index(eidx, (long long)N_EDGESC + warp);
    const float4* hs4 = (const float4*)hs;
    float4 v = hs4[(size_t)src * 32 + lane];
    float* a = agg + (size_t)dst * 128 + lane * 4;
    red_add_v4(a, v);
}

// ---------------- post: h = relu(agg * dis + b) -----------------------------------
__global__ void post_relu_kernel(const float* __restrict__ agg,
                                 const float* __restrict__ b,
                                 float* __restrict__ hout) {
    int i = blockIdx.x * blockDim.x + threadIdx.x;   // over N*32 float4s
    if (i >= N_NODESC * 32) return;
    int node = i >> 5, c4 = i & 31;
    float s = g_dis[node];
    float4 a  = ((const float4*)agg)[i];
    float4 bb = ((const float4*)b)[c4];
    float4 r;
    r.x = fmaxf(fmaf(a.x, s, bb.x), 0.f);
    r.y = fmaxf(fmaf(a.y, s, bb.y), 0.f);
    r.z = fmaxf(fmaf(a.z, s, bb.z), 0.f);
    r.w = fmaxf(fmaf(a.w, s, bb.w), 0.f);
    ((float4*)hout)[i] = r;
}

// ---------------- layer-2 post fused with graph pooling --------------------------
__global__ void post_pool_kernel(const void* __restrict__ batch,
                                 const float* __restrict__ agg,
                                 const float* __restrict__ b,
                                 float* __restrict__ pool) {
    int i = blockIdx.x * blockDim.x + threadIdx.x;
    if (i >= N_NODESC * 32) return;
    int node = i >> 5, c4 = i & 31;
    float s = g_dis[node];
    float4 a  = ((const float4*)agg)[i];
    float4 bb = ((const float4*)b)[c4];
    float4 r;
    r.x = fmaxf(fmaf(a.x, s, bb.x), 0.f);
    r.y = fmaxf(fmaf(a.y, s, bb.y), 0.f);
    r.z = fmaxf(fmaf(a.z, s, bb.z), 0.f);
    r.w = fmaxf(fmaf(a.w, s, bb.w), 0.f);
    int g = load_index(batch, node);
    red_add_v4(pool + g * HIDC + c4 * 4, r);
}

__global__ void zero_pool_kernel(float* __restrict__ pool, float* __restrict__ cnt) {
    int i = blockIdx.x * blockDim.x + threadIdx.x;
    if (i < N_GRAPHSC * HIDC) pool[i] = 0.f;
    if (i < N_GRAPHSC) cnt[i] = 0.f;
}

__global__ void count_kernel(const void* __restrict__ batch, float* __restrict__ cnt) {
    int i = blockIdx.x * blockDim.x + threadIdx.x;
    if (i >= N_NODESC) return;
    int g = load_index(batch, i);
    atomicAdd(&cnt[g], 1.f);
}

// ---------------- FC head: out = (pool/cnt) @ Wfc + bfc --------------------------
__global__ void final_kernel(const float* __restrict__ pool,
                             const float* __restrict__ cnt,
                             const float* __restrict__ Wfc,
                             const float* __restrict__ bfc,
                             float* __restrict__ out) {
    int t = threadIdx.x;
    if (t >= N_GRAPHSC * OUTC) return;
    int g = t >> 4, o = t & 15;
    float sum = 0.f;
#pragma unroll 8
    for (int c = 0; c < HIDC; c++)
        sum = fmaf(pool[g * HIDC + c], Wfc[c * OUTC + o], sum);
    float c = fmaxf(cnt[g], 1.f);
    out[g * OUTC + o] = sum / c + bfc[o];
}

// ---------------- launcher -------------------------------------------------------
extern "C" void kernel_launch(void* const* d_in, const int* in_sizes, int n_in,
                              void* d_out, int out_size) {
    const float* x    = (const float*)d_in[0];
    const void*  eidx = d_in[1];
    const void*  bat  = d_in[2];
    const float* W1   = (const float*)d_in[3];
    const float* b1   = (const float*)d_in[4];
    const float* W2   = (const float*)d_in[5];
    const float* b2   = (const float*)d_in[6];
    const float* Wfc  = (const float*)d_in[7];
    const float* bfc  = (const float*)d_in[8];
    float* out = (float*)d_out;

    // Resolve REAL device addresses for the scratch globals.
    void *p_hs = nullptr, *p_agg = nullptr, *p_h = nullptr, *p_pool = nullptr, *p_cnt = nullptr;
    cudaGetSymbolAddress(&p_hs,   g_hs);
    cudaGetSymbolAddress(&p_agg,  g_agg);
    cudaGetSymbolAddress(&p_h,    g_h);
    cudaGetSymbolAddress(&p_pool, g_pool);
    cudaGetSymbolAddress(&p_cnt,  g_cnt);
    float* hs   = (float*)p_hs;
    float* agg  = (float*)p_agg;
    float* h    = (float*)p_h;
    float* pool = (float*)p_pool;
    float* cnt  = (float*)p_cnt;

    const int T = 256;
    const int nodeBlocks  = (N_NODESC + T - 1) / T;
    const int edgeBlocks  = (N_EDGESC + T - 1) / T;
    const long long edgeThreads = (long long)N_EDGESC * 32;
    const int edgeWarpBlk = (int)((edgeThreads + T - 1) / T);    // warp per edge
    const int chanBlocks  = (N_NODESC * 32 + T - 1) / T;         // float4 per thread
    const int gemmBlocks  = (N_NODESC + 127) / 128;

    detect_kernel<<<1, 64>>>(eidx);                              // launch 0
    deg_init_kernel<<<nodeBlocks, T>>>();                        // launch 1
    deg_accum_kernel<<<edgeBlocks, T>>>(eidx);                   // launch 2
    dis_kernel<<<nodeBlocks, T>>>();                             // launch 3

    // ---- layer 1 (agg initialized by GEMM epilogue = self-loop term) ----
    gemm_scale_kernel<<<gemmBlocks, 256>>>(x, W1, hs, agg, N_NODESC);   // launch 4
    edge_scatter_kernel<<<edgeWarpBlk, T>>>(eidx, hs, agg);             // launch 5 (ncu target)
    post_relu_kernel<<<chanBlocks, T>>>(agg, b1, h);

    // ---- layer 2 ----
    gemm_scale_kernel<<<gemmBlocks, 256>>>(h, W2, hs, agg, N_NODESC);
    edge_scatter_kernel<<<edgeWarpBlk, T>>>(eidx, hs, agg);

    // ---- pooling + head ----
    zero_pool_kernel<<<(N_GRAPHSC * HIDC + T - 1) / T, T>>>(pool, cnt);
    count_kernel<<<nodeBlocks, T>>>(bat, cnt);
    post_pool_kernel<<<chanBlocks, T>>>(bat, agg, b2, pool);
    final_kernel<<<1, 1024>>>(pool, cnt, Wfc, bfc, out);
}

// round 7
// speedup vs baseline: 1.2450x; 1.2419x over previous
#include <cuda_runtime.h>
#include <stdint.h>

#define N_NODESC 50000
#define N_EDGESC 800000
#define N_GRAPHSC 64
#define HIDC 128
#define OUTC 16
#define SCAN_T 1024

// ---------------- scratch (device globals; no allocation allowed) ----------------
__device__ int   g_is64;
__device__ int   g_deg [N_NODESC];          // degree incl. self-loop
__device__ float g_dis [N_NODESC];
__device__ int   g_roff[N_NODESC + 1];      // CSR row offsets (in-edges, excl self)
__device__ int   g_cur [N_NODESC];          // fill cursors
__device__ int   g_csrc[N_EDGESC];          // CSR column (src) indices
__device__ float g_hs  [(size_t)N_NODESC * HIDC];  // GEMM output (unscaled)
__device__ float g_h   [(size_t)N_NODESC * HIDC];  // layer-1 activation
__device__ float g_pool[N_GRAPHSC * HIDC];
__device__ float g_cnt [N_GRAPHSC];

__device__ __forceinline__ int load_index(const void* p, long long i) {
    if (g_is64) return (int)((const long long*)p)[i];
    return ((const int*)p)[i];
}

__device__ __forceinline__ void red_add_v4(float* addr, float4 v) {
    asm volatile("red.global.add.v4.f32 [%0], {%1,%2,%3,%4};"
                 :: "l"(addr), "f"(v.x), "f"(v.y), "f"(v.z), "f"(v.w) : "memory");
}

// ---- launch 0: prolog — dtype detect + deg=1 init + pool/cnt zero ---------------
__global__ void prolog_kernel(const void* eidx, float* __restrict__ pool,
                              float* __restrict__ cnt) {
    int i = blockIdx.x * blockDim.x + threadIdx.x;
    if (i < N_NODESC) g_deg[i] = 1;                    // self-loop
    if (i < N_GRAPHSC * HIDC) pool[i] = 0.f;
    if (i < N_GRAPHSC) cnt[i] = 0.f;
    if (i == 0) {
        const long long* q = (const long long*)eidx;
        int is64 = 1;
        for (int k = 0; k < 64; k++) {
            long long v = q[k];
            if (v < 0 || v >= (long long)N_NODESC) { is64 = 0; break; }
        }
        g_is64 = is64;
    }
}

// ---- launch 1: degree accumulation ----------------------------------------------
__global__ void deg_accum_kernel(const void* __restrict__ eidx) {
    int e = blockIdx.x * blockDim.x + threadIdx.x;
    if (e >= N_EDGESC) return;
    int dst = load_index(eidx, (long long)N_EDGESC + e);
    atomicAdd(&g_deg[dst], 1);
}

// ---- launch 2: single-block exclusive scan of (deg-1) -> roff, cur --------------
__global__ __launch_bounds__(SCAN_T)
void scan_kernel() {
    __shared__ int part[SCAN_T];
    const int t = threadIdx.x;
    const int chunk = (N_NODESC + SCAN_T - 1) / SCAN_T;   // 49
    int beg = t * chunk;
    int end = beg + chunk; if (end > N_NODESC) end = N_NODESC;
    int s = 0;
    for (int i = beg; i < end; i++) s += g_deg[i] - 1;
    part[t] = s;
    __syncthreads();
    // Hillis-Steele inclusive scan
    for (int off = 1; off < SCAN_T; off <<= 1) {
        int v = (t >= off) ? part[t - off] : 0;
        __syncthreads();
        part[t] += v;
        __syncthreads();
    }
    int base = (t == 0) ? 0 : part[t - 1];
    for (int i = beg; i < end; i++) {
        g_roff[i] = base;
        g_cur[i]  = base;
        base += g_deg[i] - 1;
    }
    if (t == SCAN_T - 1) g_roff[N_NODESC] = base;
}

// ---- launch 3 (PROFILED): GEMM C = A @ W  (M x 128 x 128), K-tile 16 ------------
__global__ __launch_bounds__(256)
void gemm_kernel(const float* __restrict__ A, const float* __restrict__ W,
                 float* __restrict__ C, int M) {
    __shared__ float As[16][128];
    __shared__ float Bs[16][128];
    const int tid  = threadIdx.x;
    const int tx   = tid & 15;
    const int ty   = tid >> 4;
    const int row0 = blockIdx.x * 128;

    float acc[8][8];
#pragma unroll
    for (int i = 0; i < 8; i++)
#pragma unroll
        for (int j = 0; j < 8; j++) acc[i][j] = 0.f;

    for (int k0 = 0; k0 < 128; k0 += 16) {
#pragma unroll
        for (int u = 0; u < 2; u++) {
            int idx  = tid + u * 256;
            int r    = idx & 127;
            int cg   = idx >> 7;
            int grow = row0 + r;
            float4 av = make_float4(0.f, 0.f, 0.f, 0.f);
            if (grow < M) av = *(const float4*)(A + (size_t)grow * 128 + k0 + cg * 4);
            As[cg * 4 + 0][r] = av.x;
            As[cg * 4 + 1][r] = av.y;
            As[cg * 4 + 2][r] = av.z;
            As[cg * 4 + 3][r] = av.w;
        }
#pragma unroll
        for (int u = 0; u < 2; u++) {
            int idx = tid + u * 256;
            int br  = idx >> 5;
            int bc  = (idx & 31) * 4;
            *(float4*)&Bs[br][bc] = *(const float4*)(W + (size_t)(k0 + br) * 128 + bc);
        }
        __syncthreads();

#pragma unroll
        for (int k = 0; k < 16; k++) {
            float am[8], bn[8];
            *(float4*)&am[0] = *(const float4*)&As[k][ty * 8 + 0];
            *(float4*)&am[4] = *(const float4*)&As[k][ty * 8 + 4];
            *(float4*)&bn[0] = *(const float4*)&Bs[k][tx * 8 + 0];
            *(float4*)&bn[4] = *(const float4*)&Bs[k][tx * 8 + 4];
#pragma unroll
            for (int i = 0; i < 8; i++)
#pragma unroll
                for (int j = 0; j < 8; j++)
                    acc[i][j] = fmaf(am[i], bn[j], acc[i][j]);
        }
        __syncthreads();
    }

#pragma unroll
    for (int i = 0; i < 8; i++) {
        int r = row0 + ty * 8 + i;
        if (r < M) {
#pragma unroll
            for (int j = 0; j < 8; j += 4)
                *(float4*)(C + (size_t)r * 128 + tx * 8 + j) =
                    make_float4(acc[i][j], acc[i][j+1], acc[i][j+2], acc[i][j+3]);
        }
    }
}

// ---- launch 4: dis = rsqrt(deg) --------------------------------------------------
__global__ void dis_kernel() {
    int i = blockIdx.x * blockDim.x + threadIdx.x;
    if (i < N_NODESC) g_dis[i] = rsqrtf((float)g_deg[i]);
}

// ---- launch 5: CSR fill (counting sort by dst) ----------------------------------
__global__ void csr_fill_kernel(const void* __restrict__ eidx) {
    int e = blockIdx.x * blockDim.x + threadIdx.x;
    if (e >= N_EDGESC) return;
    int src = load_index(eidx, e);
    int dst = load_index(eidx, (long long)N_EDGESC + e);
    int pos = atomicAdd(&g_cur[dst], 1);
    g_csrc[pos] = src;
}

// ---- gather aggregation: warp per node, fused post ------------------------------
// acc = h[n]*dis[n] + sum_{src in CSR[n]} h[src]*dis[src];  out = relu(acc*dis[n]+b)
__global__ __launch_bounds__(256)
void agg_relu_kernel(const float* __restrict__ h, const float* __restrict__ b,
                     float* __restrict__ out) {
    int n    = (blockIdx.x * blockDim.x + threadIdx.x) >> 5;
    int lane = threadIdx.x & 31;
    if (n >= N_NODESC) return;
    const float4* h4 = (const float4*)h;
    float sn = g_dis[n];
    float4 self = h4[(size_t)n * 32 + lane];
    float4 acc = make_float4(self.x * sn, self.y * sn, self.z * sn, self.w * sn);
    int beg = g_roff[n], end = g_roff[n + 1];
#pragma unroll 2
    for (int e = beg; e < end; e++) {
        int s = g_csrc[e];
        float ds = g_dis[s];
        float4 v = h4[(size_t)s * 32 + lane];
        acc.x = fmaf(v.x, ds, acc.x);
        acc.y = fmaf(v.y, ds, acc.y);
        acc.z = fmaf(v.z, ds, acc.z);
        acc.w = fmaf(v.w, ds, acc.w);
    }
    float4 bb = ((const float4*)b)[lane];
    float4 r;
    r.x = fmaxf(fmaf(acc.x, sn, bb.x), 0.f);
    r.y = fmaxf(fmaf(acc.y, sn, bb.y), 0.f);
    r.z = fmaxf(fmaf(acc.z, sn, bb.z), 0.f);
    r.w = fmaxf(fmaf(acc.w, sn, bb.w), 0.f);
    ((float4*)out)[(size_t)n * 32 + lane] = r;
}

// ---- layer-2 gather fused with relu + graph pooling + count ---------------------
__global__ __launch_bounds__(256)
void agg_pool_kernel(const float* __restrict__ h, const float* __restrict__ b,
                     const void* __restrict__ batch,
                     float* __restrict__ pool, float* __restrict__ cnt) {
    int n    = (blockIdx.x * blockDim.x + threadIdx.x) >> 5;
    int lane = threadIdx.x & 31;
    if (n >= N_NODESC) return;
    const float4* h4 = (const float4*)h;
    float sn = g_dis[n];
    float4 self = h4[(size_t)n * 32 + lane];
    float4 acc = make_float4(self.x * sn, self.y * sn, self.z * sn, self.w * sn);
    int beg = g_roff[n], end = g_roff[n + 1];
#pragma unroll 2
    for (int e = beg; e < end; e++) {
        int s = g_csrc[e];
        float ds = g_dis[s];
        float4 v = h4[(size_t)s * 32 + lane];
        acc.x = fmaf(v.x, ds, acc.x);
        acc.y = fmaf(v.y, ds, acc.y);
        acc.z = fmaf(v.z, ds, acc.z);
        acc.w = fmaf(v.w, ds, acc.w);
    }
    float4 bb = ((const float4*)b)[lane];
    float4 r;
    r.x = fmaxf(fmaf(acc.x, sn, bb.x), 0.f);
    r.y = fmaxf(fmaf(acc.y, sn, bb.y), 0.f);
    r.z = fmaxf(fmaf(acc.z, sn, bb.z), 0.f);
    r.w = fmaxf(fmaf(acc.w, sn, bb.w), 0.f);
    int g = load_index(batch, n);
    red_add_v4(pool + g * HIDC + lane * 4, r);
    if (lane == 0) atomicAdd(&cnt[g], 1.f);
}

// ---- FC head --------------------------------------------------------------------
__global__ void final_kernel(const float* __restrict__ pool,
                             const float* __restrict__ cnt,
                             const float* __restrict__ Wfc,
                             const float* __restrict__ bfc,
                             float* __restrict__ out) {
    int t = threadIdx.x;
    if (t >= N_GRAPHSC * OUTC) return;
    int g = t >> 4, o = t & 15;
    float sum = 0.f;
#pragma unroll 8
    for (int c = 0; c < HIDC; c++)
        sum = fmaf(pool[g * HIDC + c], Wfc[c * OUTC + o], sum);
    float c = fmaxf(cnt[g], 1.f);
    out[g * OUTC + o] = sum / c + bfc[o];
}

// ---- launcher -------------------------------------------------------------------
extern "C" void kernel_launch(void* const* d_in, const int* in_sizes, int n_in,
                              void* d_out, int out_size) {
    const float* x    = (const float*)d_in[0];
    const void*  eidx = d_in[1];
    const void*  bat  = d_in[2];
    const float* W1   = (const float*)d_in[3];
    const float* b1   = (const float*)d_in[4];
    const float* W2   = (const float*)d_in[5];
    const float* b2   = (const float*)d_in[6];
    const float* Wfc  = (const float*)d_in[7];
    const float* bfc  = (const float*)d_in[8];
    float* out = (float*)d_out;

    void *p_hs = nullptr, *p_h = nullptr, *p_pool = nullptr, *p_cnt = nullptr;
    cudaGetSymbolAddress(&p_hs,   g_hs);
    cudaGetSymbolAddress(&p_h,    g_h);
    cudaGetSymbolAddress(&p_pool, g_pool);
    cudaGetSymbolAddress(&p_cnt,  g_cnt);
    float* hs   = (float*)p_hs;
    float* h    = (float*)p_h;
    float* pool = (float*)p_pool;
    float* cnt  = (float*)p_cnt;

    const int T = 256;
    const int nodeBlocks = (N_NODESC + T - 1) / T;
    const int edgeBlocks = (N_EDGESC + T - 1) / T;
    const int warpBlocks = (int)(((long long)N_NODESC * 32 + T - 1) / T);
    const int gemmBlocks = (N_NODESC + 127) / 128;

    prolog_kernel<<<nodeBlocks, T>>>(eidx, pool, cnt);          // 0
    deg_accum_kernel<<<edgeBlocks, T>>>(eidx);                  // 1
    scan_kernel<<<1, SCAN_T>>>();                               // 2
    gemm_kernel<<<gemmBlocks, 256>>>(x, W1, hs, N_NODESC);      // 3  <- profiled
    dis_kernel<<<nodeBlocks, T>>>();                            // 4
    csr_fill_kernel<<<edgeBlocks, T>>>(eidx);                   // 5

    agg_relu_kernel<<<warpBlocks, T>>>(hs, b1, h);              // 6  layer-1 fused
    gemm_kernel<<<gemmBlocks, 256>>>(h, W2, hs, N_NODESC);      // 7
    agg_pool_kernel<<<warpBlocks, T>>>(hs, b2, bat, pool, cnt); // 8  layer-2 fused
    final_kernel<<<1, 1024>>>(pool, cnt, Wfc, bfc, out);        // 9
}

// round 14
// speedup vs baseline: 1.3472x; 1.0821x over previous
#include <cuda_runtime.h>
#include <stdint.h>

#define N_NODESC 50000
#define N_EDGESC 800000
#define N_GRAPHSC 64
#define HIDC 128
#define OUTC 16
#define SCAN_T 1024

// ---------------- scratch (device globals; no allocation allowed) ----------------
__device__ int   g_is64;
__device__ int   g_deg [N_NODESC];          // degree incl. self-loop
__device__ float g_dis [N_NODESC];
__device__ int   g_roff[N_NODESC + 1];      // CSR row offsets (in-edges, excl self)
__device__ int   g_cur [N_NODESC];          // fill cursors
__device__ int   g_csrc[N_EDGESC];          // CSR column (src) indices
__device__ float g_hs  [(size_t)N_NODESC * HIDC];  // GEMM output (unscaled)
__device__ float g_h   [(size_t)N_NODESC * HIDC];  // layer-1 activation
__device__ float g_pool[N_GRAPHSC * HIDC];
__device__ float g_cnt [N_GRAPHSC];

__device__ __forceinline__ int load_index(const void* p, long long i) {
    if (g_is64) return (int)((const long long*)p)[i];
    return ((const int*)p)[i];
}

__device__ __forceinline__ void red_add_v4(float* addr, float4 v) {
    asm volatile("red.global.add.v4.f32 [%0], {%1,%2,%3,%4};"
                 :: "l"(addr), "f"(v.x), "f"(v.y), "f"(v.z), "f"(v.w) : "memory");
}

__device__ __forceinline__ uint32_t f2tf32(float x) {
    uint32_t r;
    asm("cvt.rna.tf32.f32 %0, %1;" : "=r"(r) : "f"(x));
    return r;
}

__device__ __forceinline__ void mma_tf32(float c[4], const uint32_t a[4], const uint32_t b[2]) {
    asm volatile("mma.sync.aligned.m16n8k8.row.col.f32.tf32.tf32.f32 "
                 "{%0,%1,%2,%3}, {%4,%5,%6,%7}, {%8,%9}, {%0,%1,%2,%3};"
                 : "+f"(c[0]), "+f"(c[1]), "+f"(c[2]), "+f"(c[3])
                 : "r"(a[0]), "r"(a[1]), "r"(a[2]), "r"(a[3]),
                   "r"(b[0]), "r"(b[1]));
}

// ---- launch 0: prolog — dtype detect + deg=1 init + pool/cnt zero ---------------
__global__ void prolog_kernel(const void* eidx, float* __restrict__ pool,
                              float* __restrict__ cnt) {
    int i = blockIdx.x * blockDim.x + threadIdx.x;
    if (i < N_NODESC) g_deg[i] = 1;                    // self-loop
    if (i < N_GRAPHSC * HIDC) pool[i] = 0.f;
    if (i < N_GRAPHSC) cnt[i] = 0.f;
    if (i == 0) {
        const long long* q = (const long long*)eidx;
        int is64 = 1;
        for (int k = 0; k < 64; k++) {
            long long v = q[k];
            if (v < 0 || v >= (long long)N_NODESC) { is64 = 0; break; }
        }
        g_is64 = is64;
    }
}

// ---- launch 1: degree accumulation ----------------------------------------------
__global__ void deg_accum_kernel(const void* __restrict__ eidx) {
    int e = blockIdx.x * blockDim.x + threadIdx.x;
    if (e >= N_EDGESC) return;
    int dst = load_index(eidx, (long long)N_EDGESC + e);
    atomicAdd(&g_deg[dst], 1);
}

// ---- launch 2: single-block exclusive scan of (deg-1) -> roff, cur --------------
__global__ __launch_bounds__(SCAN_T)
void scan_kernel() {
    __shared__ int part[SCAN_T];
    const int t = threadIdx.x;
    const int chunk = (N_NODESC + SCAN_T - 1) / SCAN_T;   // 49
    int beg = t * chunk;
    int end = beg + chunk; if (end > N_NODESC) end = N_NODESC;
    int s = 0;
    for (int i = beg; i < end; i++) s += g_deg[i] - 1;
    part[t] = s;
    __syncthreads();
    for (int off = 1; off < SCAN_T; off <<= 1) {
        int v = (t >= off) ? part[t - off] : 0;
        __syncthreads();
        part[t] += v;
        __syncthreads();
    }
    int base = (t == 0) ? 0 : part[t - 1];
    for (int i = beg; i < end; i++) {
        g_roff[i] = base;
        g_cur[i]  = base;
        base += g_deg[i] - 1;
    }
    if (t == SCAN_T - 1) g_roff[N_NODESC] = base;
}

// ---- launch 3 (PROFILED): tensor-core tf32 GEMM, 3xTF32 split -------------------
// C[M,128] = A[M,128] @ W[128,128], fp32-accurate via Ab*Wb + Ab*Ws + As*Wb.
// Block: 256 thr / 8 warps, tile 128x128, k-chunk 16. Warp tile 32x64.
__global__ __launch_bounds__(256)
void gemm_tf32_kernel(const float* __restrict__ A, const float* __restrict__ W,
                      float* __restrict__ C, int M) {
    // A pitch 20: bank(20g+t) covers all 32 banks; B pitch 136 (==8 mod 32): 8t+g.
    __shared__ float Abig[128][20], Asml[128][20];
    __shared__ float Bbig[16][136], Bsml[16][136];

    const int tid    = threadIdx.x;
    const int wid    = tid >> 5;
    const int lane   = tid & 31;
    const int g      = lane >> 2;      // 0..7
    const int t      = lane & 3;       // 0..3
    const int warp_m = wid >> 1;       // 0..3
    const int warp_n = wid & 1;        // 0..1
    const int row0   = blockIdx.x * 128;
    const int m_base = warp_m * 32;
    const int n_base = warp_n * 64;

    float c[2][8][4];
#pragma unroll
    for (int ma = 0; ma < 2; ma++)
#pragma unroll
        for (int na = 0; na < 8; na++)
#pragma unroll
            for (int q = 0; q < 4; q++) c[ma][na][q] = 0.f;

    for (int k0 = 0; k0 < 128; k0 += 16) {
        // Load A chunk: 128 rows x 16 k = 512 float4, 2 per thread.
#pragma unroll
        for (int u = 0; u < 2; u++) {
            int idx = tid + u * 256;
            int r   = idx >> 2;          // 0..127
            int c4  = (idx & 3) * 4;     // 0,4,8,12
            float4 v = make_float4(0.f, 0.f, 0.f, 0.f);
            if (row0 + r < M) v = *(const float4*)(A + (size_t)(row0 + r) * 128 + k0 + c4);
            float vv[4] = {v.x, v.y, v.z, v.w};
#pragma unroll
            for (int j = 0; j < 4; j++) {
                float big = __uint_as_float(f2tf32(vv[j]));
                Abig[r][c4 + j] = big;
                Asml[r][c4 + j] = __uint_as_float(f2tf32(vv[j] - big));
            }
        }
        // Load B chunk: 16 rows x 128 n = 512 float4, 2 per thread.
#pragma unroll
        for (int u = 0; u < 2; u++) {
            int idx = tid + u * 256;
            int r   = idx >> 5;          // 0..15
            int c4  = (idx & 31) * 4;    // 0..124
            float4 v = *(const float4*)(W + (size_t)(k0 + r) * 128 + c4);
            float vv[4] = {v.x, v.y, v.z, v.w};
#pragma unroll
            for (int j = 0; j < 4; j++) {
                float big = __uint_as_float(f2tf32(vv[j]));
                Bbig[r][c4 + j] = big;
                Bsml[r][c4 + j] = __uint_as_float(f2tf32(vv[j] - big));
            }
        }
        __syncthreads();

#pragma unroll
        for (int ks = 0; ks < 16; ks += 8) {
            uint32_t ab[2][4], as[2][4], bb[8][2], bs[8][2];
#pragma unroll
            for (int ma = 0; ma < 2; ma++) {
                int r0 = m_base + ma * 16;
                ab[ma][0] = __float_as_uint(Abig[r0 + g    ][ks + t    ]);
                ab[ma][1] = __float_as_uint(Abig[r0 + g + 8][ks + t    ]);
                ab[ma][2] = __float_as_uint(Abig[r0 + g    ][ks + t + 4]);
                ab[ma][3] = __float_as_uint(Abig[r0 + g + 8][ks + t + 4]);
                as[ma][0] = __float_as_uint(Asml[r0 + g    ][ks + t    ]);
                as[ma][1] = __float_as_uint(Asml[r0 + g + 8][ks + t    ]);
                as[ma][2] = __float_as_uint(Asml[r0 + g    ][ks + t + 4]);
                as[ma][3] = __float_as_uint(Asml[r0 + g + 8][ks + t + 4]);
            }
#pragma unroll
            for (int na = 0; na < 8; na++) {
                int n0 = n_base + na * 8;
                bb[na][0] = __float_as_uint(Bbig[ks + t    ][n0 + g]);
                bb[na][1] = __float_as_uint(Bbig[ks + t + 4][n0 + g]);
                bs[na][0] = __float_as_uint(Bsml[ks + t    ][n0 + g]);
                bs[na][1] = __float_as_uint(Bsml[ks + t + 4][n0 + g]);
            }
#pragma unroll
            for (int ma = 0; ma < 2; ma++)
#pragma unroll
                for (int na = 0; na < 8; na++) {
                    mma_tf32(c[ma][na], ab[ma], bb[na]);   // big*big
                    mma_tf32(c[ma][na], ab[ma], bs[na]);   // big*small
                    mma_tf32(c[ma][na], as[ma], bb[na]);   // small*big
                }
        }
        __syncthreads();
    }

    // Epilogue: c0,c1 -> (row g, cols 2t,2t+1); c2,c3 -> row g+8.
#pragma unroll
    for (int ma = 0; ma < 2; ma++) {
        int r_lo = row0 + m_base + ma * 16 + g;
        int r_hi = r_lo + 8;
#pragma unroll
        for (int na = 0; na < 8; na++) {
            int col = n_base + na * 8 + 2 * t;
            if (r_lo < M)
                *(float2*)(C + (size_t)r_lo * 128 + col) = make_float2(c[ma][na][0], c[ma][na][1]);
            if (r_hi < M)
                *(float2*)(C + (size_t)r_hi * 128 + col) = make_float2(c[ma][na][2], c[ma][na][3]);
        }
    }
}

// ---- launch 4: dis = rsqrt(deg) --------------------------------------------------
__global__ void dis_kernel() {
    int i = blockIdx.x * blockDim.x + threadIdx.x;
    if (i < N_NODESC) g_dis[i] = rsqrtf((float)g_deg[i]);
}

// ---- launch 5: CSR fill (counting sort by dst) ----------------------------------
__global__ void csr_fill_kernel(const void* __restrict__ eidx) {
    int e = blockIdx.x * blockDim.x + threadIdx.x;
    if (e >= N_EDGESC) return;
    int src = load_index(eidx, e);
    int dst = load_index(eidx, (long long)N_EDGESC + e);
    int pos = atomicAdd(&g_cur[dst], 1);
    g_csrc[pos] = src;
}

// ---- gather aggregation: warp per node, fused post ------------------------------
__global__ __launch_bounds__(256)
void agg_relu_kernel(const float* __restrict__ h, const float* __restrict__ b,
                     float* __restrict__ out) {
    int n    = (blockIdx.x * blockDim.x + threadIdx.x) >> 5;
    int lane = threadIdx.x & 31;
    if (n >= N_NODESC) return;
    const float4* h4 = (const float4*)h;
    float sn = g_dis[n];
    float4 self = h4[(size_t)n * 32 + lane];
    float4 acc = make_float4(self.x * sn, self.y * sn, self.z * sn, self.w * sn);
    int beg = g_roff[n], end = g_roff[n + 1];
#pragma unroll 2
    for (int e = beg; e < end; e++) {
        int s = g_csrc[e];
        float ds = g_dis[s];
        float4 v = h4[(size_t)s * 32 + lane];
        acc.x = fmaf(v.x, ds, acc.x);
        acc.y = fmaf(v.y, ds, acc.y);
        acc.z = fmaf(v.z, ds, acc.z);
        acc.w = fmaf(v.w, ds, acc.w);
    }
    float4 bb = ((const float4*)b)[lane];
    float4 r;
    r.x = fmaxf(fmaf(acc.x, sn, bb.x), 0.f);
    r.y = fmaxf(fmaf(acc.y, sn, bb.y), 0.f);
    r.z = fmaxf(fmaf(acc.z, sn, bb.z), 0.f);
    r.w = fmaxf(fmaf(acc.w, sn, bb.w), 0.f);
    ((float4*)out)[(size_t)n * 32 + lane] = r;
}

// ---- layer-2 gather fused with relu + graph pooling + count ---------------------
__global__ __launch_bounds__(256)
void agg_pool_kernel(const float* __restrict__ h, const float* __restrict__ b,
                     const void* __restrict__ batch,
                     float* __restrict__ pool, float* __restrict__ cnt) {
    int n    = (blockIdx.x * blockDim.x + threadIdx.x) >> 5;
    int lane = threadIdx.x & 31;
    if (n >= N_NODESC) return;
    const float4* h4 = (const float4*)h;
    float sn = g_dis[n];
    float4 self = h4[(size_t)n * 32 + lane];
    float4 acc = make_float4(self.x * sn, self.y * sn, self.z * sn, self.w * sn);
    int beg = g_roff[n], end = g_roff[n + 1];
#pragma unroll 2
    for (int e = beg; e < end; e++) {
        int s = g_csrc[e];
        float ds = g_dis[s];
        float4 v = h4[(size_t)s * 32 + lane];
        acc.x = fmaf(v.x, ds, acc.x);
        acc.y = fmaf(v.y, ds, acc.y);
        acc.z = fmaf(v.z, ds, acc.z);
        acc.w = fmaf(v.w, ds, acc.w);
    }
    float4 bb = ((const float4*)b)[lane];
    float4 r;
    r.x = fmaxf(fmaf(acc.x, sn, bb.x), 0.f);
    r.y = fmaxf(fmaf(acc.y, sn, bb.y), 0.f);
    r.z = fmaxf(fmaf(acc.z, sn, bb.z), 0.f);
    r.w = fmaxf(fmaf(acc.w, sn, bb.w), 0.f);
    int g = load_index(batch, n);
    red_add_v4(pool + g * HIDC + lane * 4, r);
    if (lane == 0) atomicAdd(&cnt[g], 1.f);
}

// ---- FC head --------------------------------------------------------------------
__global__ void final_kernel(const float* __restrict__ pool,
                             const float* __restrict__ cnt,
                             const float* __restrict__ Wfc,
                             const float* __restrict__ bfc,
                             float* __restrict__ out) {
    int t = threadIdx.x;
    if (t >= N_GRAPHSC * OUTC) return;
    int g = t >> 4, o = t & 15;
    float sum = 0.f;
#pragma unroll 8
    for (int c = 0; c < HIDC; c++)
        sum = fmaf(pool[g * HIDC + c], Wfc[c * OUTC + o], sum);
    float c = fmaxf(cnt[g], 1.f);
    out[g * OUTC + o] = sum / c + bfc[o];
}

// ---- launcher -------------------------------------------------------------------
extern "C" void kernel_launch(void* const* d_in, const int* in_sizes, int n_in,
                              void* d_out, int out_size) {
    const float* x    = (const float*)d_in[0];
    const void*  eidx = d_in[1];
    const void*  bat  = d_in[2];
    const float* W1   = (const float*)d_in[3];
    const float* b1   = (const float*)d_in[4];
    const float* W2   = (const float*)d_in[5];
    const float* b2   = (const float*)d_in[6];
    const float* Wfc  = (const float*)d_in[7];
    const float* bfc  = (const float*)d_in[8];
    float* out = (float*)d_out;

    void *p_hs = nullptr, *p_h = nullptr, *p_pool = nullptr, *p_cnt = nullptr;
    cudaGetSymbolAddress(&p_hs,   g_hs);
    cudaGetSymbolAddress(&p_h,    g_h);
    cudaGetSymbolAddress(&p_pool, g_pool);
    cudaGetSymbolAddress(&p_cnt,  g_cnt);
    float* hs   = (float*)p_hs;
    float* h    = (float*)p_h;
    float* pool = (float*)p_pool;
    float* cnt  = (float*)p_cnt;

    const int T = 256;
    const int nodeBlocks = (N_NODESC + T - 1) / T;
    const int edgeBlocks = (N_EDGESC + T - 1) / T;
    const int warpBlocks = (int)(((long long)N_NODESC * 32 + T - 1) / T);
    const int gemmBlocks = (N_NODESC + 127) / 128;

    prolog_kernel<<<nodeBlocks, T>>>(eidx, pool, cnt);           // 0
    deg_accum_kernel<<<edgeBlocks, T>>>(eidx);                   // 1
    scan_kernel<<<1, SCAN_T>>>();                                // 2
    gemm_tf32_kernel<<<gemmBlocks, 256>>>(x, W1, hs, N_NODESC);  // 3  <- profiled
    dis_kernel<<<nodeBlocks, T>>>();                             // 4
    csr_fill_kernel<<<edgeBlocks, T>>>(eidx);                    // 5

    agg_relu_kernel<<<warpBlocks, T>>>(hs, b1, h);               // 6
    gemm_tf32_kernel<<<gemmBlocks, 256>>>(h, W2, hs, N_NODESC);  // 7
    agg_pool_kernel<<<warpBlocks, T>>>(hs, b2, bat, pool, cnt);  // 8
    final_kernel<<<1, 1024>>>(pool, cnt, Wfc, bfc, out);         // 9
}